// round 10
// baseline (speedup 1.0000x reference)
#include <cuda_runtime.h>
#include <cstdint>

typedef unsigned long long u64;
typedef unsigned int u32;

#define NROWS 1024
#define NCOLS 16384
#define NTOT (NROWS*NCOLS)
#define CAP 32768
#define FBINS 4096
#define HLO 2.0f
#define HSCALE 1024.0f
#define BIN_MIN 1060      // value threshold ~= 3.035
#define BCAP 128

#define SC_GRID 4096
#define SC_BLK 256
#define SC_STRIDE (SC_GRID*SC_BLK)   // NTOT/4 = 4*SC_STRIDE exactly

#define STAGE_KEYS 10240
#define STAGE_WINS (STAGE_KEYS/32)   // 320
#define FLAT_INVALID 0xFFFFFFFFu

#define SB_WARPS 8

// device-global scratch (no allocations allowed)
// Self-cleaning invariant: at kernel_launch entry, g_bincnt[]==0 and
// g_total==g_overflow==0 (zero-init at load; re-established every call:
// k_sortbins zeroes bincnt, k_final resets total/overflow).
__device__ u32 g_bincnt[FBINS];
__device__ u32 g_binoff[FBINS];
__device__ u32 g_total;
__device__ u32 g_overflow;
__device__ u64 g_bucket[FBINS * BCAP];   // 4 MB
__device__ u64 g_keys[CAP];

__device__ __forceinline__ int binof(float v) {
    int b = (int)((v - HLO) * HSCALE);
    return (b > FBINS - 1) ? (FBINS - 1) : b;
}

// ONE full-matrix pass: scatter candidates (binof(v) >= BIN_MIN) into buckets
__global__ void __launch_bounds__(SC_BLK)
k_scatter(const float4* __restrict__ c4) {
    int idx = blockIdx.x * SC_BLK + threadIdx.x;
    float4 vv[4];
    #pragma unroll
    for (int k = 0; k < 4; k++) vv[k] = __ldcs(&c4[idx + k * SC_STRIDE]);   // streaming, MLP=4
    #pragma unroll
    for (int k = 0; k < 4; k++) {
        int i = idx + k * SC_STRIDE;
        float a[4] = { vv[k].x, vv[k].y, vv[k].z, vv[k].w };
        #pragma unroll
        for (int q = 0; q < 4; q++) {
            if (a[q] >= 3.0f) {
                int b = binof(a[q]);
                if (b >= BIN_MIN) {
                    u32 pos = atomicAdd(&g_bincnt[b], 1u);
                    if (pos < BCAP) {
                        u32 flat = (u32)(i * 4 + q);
                        u32 enc = __float_as_uint(a[q]);  // candidates > 0: bits order-preserving
                        g_bucket[b * BCAP + pos] = ((u64)enc << 24) | (u64)(0xFFFFFFu - flat);
                    } else {
                        g_overflow = 1;
                    }
                }
            }
        }
    }
}

// one block: suffix-sum bucket counts (descending bins) via shuffle scan
__global__ void __launch_bounds__(1024)
k_scan() {
    __shared__ u32 warpsum[32];
    int tid = threadIdx.x;
    int lane = tid & 31, w = tid >> 5;

    u32 x[4], pre[4];
    u32 run = 0;
    #pragma unroll
    for (int q = 0; q < 4; q++) {
        int b = FBINS - 1 - (tid * 4 + q);
        x[q] = g_bincnt[b];
        pre[q] = run;
        run += x[q];
    }
    // warp-inclusive scan of run
    u32 v = run;
    #pragma unroll
    for (int o = 1; o < 32; o <<= 1) {
        u32 t = __shfl_up_sync(0xFFFFFFFFu, v, o);
        if (lane >= o) v += t;
    }
    if (lane == 31) warpsum[w] = v;
    __syncthreads();
    if (w == 0) {
        u32 s = warpsum[lane];
        #pragma unroll
        for (int o = 1; o < 32; o <<= 1) {
            u32 t = __shfl_up_sync(0xFFFFFFFFu, s, o);
            if (lane >= o) s += t;
        }
        warpsum[lane] = s;
    }
    __syncthreads();
    u32 excl = v - run + ((w > 0) ? warpsum[w - 1] : 0u);

    #pragma unroll
    for (int q = 0; q < 4; q++) {
        int b = FBINS - 1 - (tid * 4 + q);
        u32 S = excl + pre[q] + x[q];
        g_binoff[b] = S - x[q];
    }
    if (tid == 0) {
        u32 total = warpsum[31];
        if (total > CAP) { g_overflow = 1; total = 0; }
        g_total = total;
    }
}

// warp-per-bin: sort bucket desc (<=128 elems) into g_keys; self-clean bincnt
__global__ void __launch_bounds__(SB_WARPS * 32)
k_sortbins() {
    __shared__ u64 sk[SB_WARPS][BCAP];
    int w = threadIdx.x >> 5, lane = threadIdx.x & 31;
    int b = blockIdx.x * SB_WARPS + w;
    u32 cnt = g_bincnt[b];
    if (lane == 0) g_bincnt[b] = 0;          // self-clean for next call
    if (cnt == 0) return;
    if (cnt > BCAP) cnt = BCAP;              // overflow already flagged; data unused
    u32 off = g_binoff[b];
    if (cnt == 1) { if (lane == 0) g_keys[off] = g_bucket[b * BCAP]; return; }

    u32 m = 2; while (m < cnt) m <<= 1;      // m <= 128
    for (u32 i = lane; i < m; i += 32) sk[w][i] = (i < cnt) ? g_bucket[b * BCAP + i] : 0ull;
    __syncwarp();
    for (u32 k = 2; k <= m; k <<= 1) {
        for (u32 j = k >> 1; j > 0; j >>= 1) {
            for (u32 i = lane; i < m; i += 32) {
                u32 p = i ^ j;
                if (p > i) {
                    u64 a = sk[w][i], bb = sk[w][p];
                    bool desc = ((i & k) == 0);
                    if (desc ? (a < bb) : (a > bb)) { sk[w][i] = bb; sk[w][p] = a; }
                }
            }
            __syncwarp();
        }
    }
    for (u32 i = lane; i < cnt; i += 32) g_keys[off + i] = sk[w][i];
}

__device__ __forceinline__ bool bit_test(const u32* bits, int i) {
    return (bits[i >> 5] >> (i & 31)) & 1u;
}

// greedy scan over globally-descending keys + exact fallback + output
__global__ void __launch_bounds__(1024, 1)
k_final(const float* __restrict__ cost, float* __restrict__ out, int out_size) {
    __shared__ u32 sFlat[STAGE_KEYS];          // 40960 B
    __shared__ u32 sConf[STAGE_WINS];          // 1280 B
    __shared__ u32 colUsed[NCOLS / 32];        // 2048 B
    __shared__ u32 rowUsed[NROWS / 32];        // 128 B
    __shared__ unsigned short colOf[NROWS];    // 2048 B
    __shared__ u64 redBuf[32];
    __shared__ int scnt_s;

    int tid = threadIdx.x;
    int lane = tid & 31;
    int wid = tid >> 5;
    u32 total = g_total;
    if (g_overflow) total = 0;   // pathological: pure-fallback path (exact)

    for (int i = tid; i < NCOLS / 32; i += 1024) colUsed[i] = 0;
    for (int i = tid; i < NROWS / 32; i += 1024) rowUsed[i] = 0;
    for (int i = tid; i < NROWS; i += 1024) colOf[i] = 0;
    if (tid == 0) scnt_s = 0;

    // ---- stage first STAGE_KEYS flats into shared (all warps) ----
    for (int i = tid; i < STAGE_KEYS; i += 1024)
        sFlat[i] = (i < (int)total) ? (0xFFFFFFu - (u32)(g_keys[i] & 0xFFFFFFu))
                                    : FLAT_INVALID;
    __syncthreads();

    // ---- precompute per-window conflict masks (all warps in parallel) ----
    for (int w = wid; w < STAGE_WINS; w += 32) {
        u32 flat = sFlat[w * 32 + lane];
        bool v = (flat != FLAT_INVALID);
        u32 rkey = v ? (flat >> 14) : (u32)(NROWS + lane);
        u32 ckey = v ? (flat & 0x3FFF) : (u32)(NCOLS + lane);
        u32 mR = __match_any_sync(0xFFFFFFFFu, rkey);
        u32 mC = __match_any_sync(0xFFFFFFFFu, ckey);
        u32 earlier = (1u << lane) - 1u;
        bool conf = (((mR | mC) & earlier) != 0u);
        u32 cm = __ballot_sync(0xFFFFFFFFu, conf);
        if (lane == 0) sConf[w] = cm;
    }
    __syncthreads();

    // ---- warp 0: greedy scan (prefetched windows, conditional quest) ----
    if (wid == 0) {
        int assigned = 0;
        int lim = ((int)total < STAGE_KEYS) ? (int)total : STAGE_KEYS;
        int base = 0;
        u32 flat = (0 < lim) ? sFlat[lane] : FLAT_INVALID;
        for (; base < lim && assigned < NROWS; base += 32) {
            u32 nflat = (base + 32 < STAGE_KEYS) ? sFlat[base + 32 + lane] : FLAT_INVALID;
            u32 conf = sConf[base >> 5];
            int r = (int)(flat >> 14);
            int c = (int)(flat & 0x3FFF);
            bool valid = (flat != FLAT_INVALID) && !bit_test(rowUsed, r) && !bit_test(colUsed, c);
            bool myconf = (conf >> lane) & 1u;
            bool acc0 = valid && !myconf;
            u32 accmask = __ballot_sync(0xFFFFFFFFu, acc0);
            if (acc0) {
                atomicOr(&rowUsed[r >> 5], 1u << (r & 31));
                atomicOr(&colUsed[c >> 5], 1u << (c & 31));
                colOf[r] = (unsigned short)c;
            }
            assigned += __popc(accmask);
            __syncwarp();

            if (conf) {    // uniform branch; quest lanes exist only if conf != 0
                u32 quest = __ballot_sync(0xFFFFFFFFu, valid && myconf);
                while (quest) {
                    int q = __ffs(quest) - 1;
                    quest &= quest - 1u;
                    int qr = __shfl_sync(0xFFFFFFFFu, r, q);
                    int qc = __shfl_sync(0xFFFFFFFFu, c, q);
                    bool ok = !bit_test(rowUsed, qr) && !bit_test(colUsed, qc);
                    if (ok) {
                        if (lane == 0) {
                            atomicOr(&rowUsed[qr >> 5], 1u << (qr & 31));
                            atomicOr(&colUsed[qc >> 5], 1u << (qc & 31));
                            colOf[qr] = (unsigned short)qc;
                        }
                        assigned++;
                        __syncwarp();
                    }
                }
            }
            flat = nflat;
        }
        // ---- legacy gmem tail (only if staged prefix exhausted) ----
        for (; base < (int)total && assigned < NROWS; base += 32) {
            int i = base + lane;
            u64 key = (i < (int)total) ? __ldg(&g_keys[i]) : 0ull;
            int flat2 = 0xFFFFFF - (int)(key & 0xFFFFFFu);
            int r = flat2 >> 14;
            int c = flat2 & 0x3FFF;
            bool valid = (key != 0ull) && !bit_test(rowUsed, r) && !bit_test(colUsed, c);
            u32 validmask = __ballot_sync(0xFFFFFFFFu, valid);
            u32 rkey = valid ? (u32)r : (u32)(NROWS + lane);
            u32 ckey = valid ? (u32)c : (u32)(NCOLS + lane);
            u32 mR = __match_any_sync(0xFFFFFFFFu, rkey);
            u32 mC = __match_any_sync(0xFFFFFFFFu, ckey);
            u32 earlier = (1u << lane) - 1u;
            bool conflictE = (((mR | mC) & earlier & validmask) != 0u);
            bool acc0 = valid && !conflictE;
            u32 accmask = __ballot_sync(0xFFFFFFFFu, acc0);
            if (acc0) {
                atomicOr(&rowUsed[r >> 5], 1u << (r & 31));
                atomicOr(&colUsed[c >> 5], 1u << (c & 31));
                colOf[r] = (unsigned short)c;
            }
            assigned += __popc(accmask);
            __syncwarp();
            u32 quest = __ballot_sync(0xFFFFFFFFu, valid && conflictE);
            while (quest) {
                int q = __ffs(quest) - 1;
                quest &= quest - 1u;
                int qr = __shfl_sync(0xFFFFFFFFu, r, q);
                int qc = __shfl_sync(0xFFFFFFFFu, c, q);
                bool ok = !bit_test(rowUsed, qr) && !bit_test(colUsed, qc);
                if (ok) {
                    if (lane == 0) {
                        atomicOr(&rowUsed[qr >> 5], 1u << (qr & 31));
                        atomicOr(&colUsed[qc >> 5], 1u << (qc & 31));
                        colOf[qr] = (unsigned short)qc;
                    }
                    assigned++;
                    __syncwarp();
                }
            }
        }
        if (lane == 0) scnt_s = assigned;
    }

    // ---- exact fallback: masked global argmax for any unassigned rows ----
    while (true) {
        __syncthreads();
        if (scnt_s >= NROWS) break;
        u64 best = 0;
        for (int i = tid; i < NTOT; i += 1024) {
            int r = i >> 14;
            if (bit_test(rowUsed, r)) continue;
            int c = i & 0x3FFF;
            if (bit_test(colUsed, c)) continue;
            float v = cost[i];
            u32 u = __float_as_uint(v);
            u32 enc = (u & 0x80000000u) ? ~u : (u | 0x80000000u);
            u64 kk = ((u64)enc << 24) | (u64)(0xFFFFFFu - (u32)i);
            if (kk > best) best = kk;
        }
        #pragma unroll
        for (int o = 16; o > 0; o >>= 1) {
            u64 t2 = __shfl_down_sync(0xFFFFFFFFu, best, o);
            if (t2 > best) best = t2;
        }
        if (lane == 0) redBuf[wid] = best;
        __syncthreads();
        if (tid < 32) {
            u64 b = redBuf[tid];
            #pragma unroll
            for (int o = 16; o > 0; o >>= 1) {
                u64 t2 = __shfl_down_sync(0xFFFFFFFFu, b, o);
                if (t2 > b) b = t2;
            }
            if (tid == 0) {
                int flat = 0xFFFFFF - (int)(b & 0xFFFFFFu);
                int r = flat >> 14, c = flat & 0x3FFF;
                rowUsed[r >> 5] |= 1u << (r & 31);
                colUsed[c >> 5] |= 1u << (c & 31);
                colOf[r] = (unsigned short)c;
                scnt_s = scnt_s + 1;
            }
        }
        __syncthreads();
    }

    // ---- write output as float32: rows (arange) then cols ----
    if (out_size >= 2 * NROWS) {
        for (int i = tid; i < NROWS; i += 1024) {
            out[i] = (float)i;
            out[NROWS + i] = (float)colOf[i];
        }
    } else {
        for (int i = tid; i < NROWS && i < out_size; i += 1024)
            out[i] = (float)colOf[i];
    }

    // ---- self-clean for next call ----
    if (tid == 0) { g_total = 0; g_overflow = 0; }
}

extern "C" void kernel_launch(void* const* d_in, const int* in_sizes, int n_in,
                              void* d_out, int out_size) {
    const float* cost = (const float*)d_in[0];
    float* out = (float*)d_out;
    (void)in_sizes; (void)n_in;

    k_scatter<<<SC_GRID, SC_BLK>>>((const float4*)cost);
    k_scan<<<1, 1024>>>();
    k_sortbins<<<FBINS / SB_WARPS, SB_WARPS * 32>>>();
    k_final<<<1, 1024>>>(cost, out, out_size);
}

// round 11
// speedup vs baseline: 1.0672x; 1.0672x over previous
#include <cuda_runtime.h>
#include <cstdint>

typedef unsigned long long u64;
typedef unsigned int u32;

#define NROWS 1024
#define NCOLS 16384
#define NTOT (NROWS*NCOLS)
#define CAP 32768
#define FBINS 4096
#define HLO 2.0f
#define HSCALE 1024.0f
#define BIN_MIN 1060      // value threshold ~= 3.035
#define BCAP 128

#define SC_GRID 4096
#define SC_BLK 256
#define SC_STRIDE (SC_GRID*SC_BLK)   // NTOT/4 = 4*SC_STRIDE exactly

#define STAGE_KEYS 10240
#define STAGE_WINS (STAGE_KEYS/32)   // 320
#define FLAT_INVALID 0xFFFFFFFFu

#define SB_WARPS 8

// device-global scratch (no allocations allowed)
// Self-cleaning invariant: at kernel_launch entry, g_bincnt[]==0 and
// g_total==g_overflow==0 (zero-init at load; re-established every call).
__device__ u32 g_bincnt[FBINS];
__device__ u32 g_binoff[FBINS];
__device__ u32 g_total;
__device__ u32 g_overflow;
__device__ u64 g_bucket[FBINS * BCAP];   // 4 MB
__device__ u64 g_keys[CAP];

__device__ __forceinline__ int binof(float v) {
    int b = (int)((v - HLO) * HSCALE);
    return (b > FBINS - 1) ? (FBINS - 1) : b;
}

// ONE full-matrix pass: scatter candidates (binof(v) >= BIN_MIN) into buckets
__global__ void __launch_bounds__(SC_BLK)
k_scatter(const float4* __restrict__ c4) {
    int idx = blockIdx.x * SC_BLK + threadIdx.x;
    float4 vv[4];
    #pragma unroll
    for (int k = 0; k < 4; k++) vv[k] = c4[idx + k * SC_STRIDE];   // MLP=4
    #pragma unroll
    for (int k = 0; k < 4; k++) {
        int i = idx + k * SC_STRIDE;
        float a[4] = { vv[k].x, vv[k].y, vv[k].z, vv[k].w };
        #pragma unroll
        for (int q = 0; q < 4; q++) {
            if (a[q] >= 3.0f) {
                int b = binof(a[q]);
                if (b >= BIN_MIN) {
                    u32 pos = atomicAdd(&g_bincnt[b], 1u);
                    if (pos < BCAP) {
                        u32 flat = (u32)(i * 4 + q);
                        u32 enc = __float_as_uint(a[q]);  // candidates > 0: bits order-preserving
                        g_bucket[b * BCAP + pos] = ((u64)enc << 24) | (u64)(0xFFFFFFu - flat);
                    } else {
                        g_overflow = 1;
                    }
                }
            }
        }
    }
}

// one block: suffix-sum bucket counts (descending bins) via shuffle scan
__global__ void __launch_bounds__(1024)
k_scan() {
    __shared__ u32 warpsum[32];
    int tid = threadIdx.x;
    int lane = tid & 31, w = tid >> 5;

    u32 x[4], pre[4];
    u32 run = 0;
    #pragma unroll
    for (int q = 0; q < 4; q++) {
        int b = FBINS - 1 - (tid * 4 + q);
        x[q] = g_bincnt[b];
        pre[q] = run;
        run += x[q];
    }
    u32 v = run;
    #pragma unroll
    for (int o = 1; o < 32; o <<= 1) {
        u32 t = __shfl_up_sync(0xFFFFFFFFu, v, o);
        if (lane >= o) v += t;
    }
    if (lane == 31) warpsum[w] = v;
    __syncthreads();
    if (w == 0) {
        u32 s = warpsum[lane];
        #pragma unroll
        for (int o = 1; o < 32; o <<= 1) {
            u32 t = __shfl_up_sync(0xFFFFFFFFu, s, o);
            if (lane >= o) s += t;
        }
        warpsum[lane] = s;
    }
    __syncthreads();
    u32 excl = v - run + ((w > 0) ? warpsum[w - 1] : 0u);

    #pragma unroll
    for (int q = 0; q < 4; q++) {
        int b = FBINS - 1 - (tid * 4 + q);
        u32 S = excl + pre[q] + x[q];
        g_binoff[b] = S - x[q];
    }
    if (tid == 0) {
        u32 total = warpsum[31];
        if (total > CAP) { g_overflow = 1; total = 0; }
        g_total = total;
    }
}

// warp-per-bin: sort bucket desc (<=128 elems) into g_keys; self-clean bincnt
__global__ void __launch_bounds__(SB_WARPS * 32)
k_sortbins() {
    __shared__ u64 sk[SB_WARPS][BCAP];
    int w = threadIdx.x >> 5, lane = threadIdx.x & 31;
    int b = blockIdx.x * SB_WARPS + w;
    u32 cnt = g_bincnt[b];
    if (lane == 0) g_bincnt[b] = 0;          // self-clean for next call
    if (cnt == 0) return;
    if (cnt > BCAP) cnt = BCAP;              // overflow already flagged; data unused
    u32 off = g_binoff[b];
    if (cnt == 1) { if (lane == 0) g_keys[off] = g_bucket[b * BCAP]; return; }

    u32 m = 2; while (m < cnt) m <<= 1;      // m <= 128
    for (u32 i = lane; i < m; i += 32) sk[w][i] = (i < cnt) ? g_bucket[b * BCAP + i] : 0ull;
    __syncwarp();
    for (u32 k = 2; k <= m; k <<= 1) {
        for (u32 j = k >> 1; j > 0; j >>= 1) {
            for (u32 i = lane; i < m; i += 32) {
                u32 p = i ^ j;
                if (p > i) {
                    u64 a = sk[w][i], bb = sk[w][p];
                    bool desc = ((i & k) == 0);
                    if (desc ? (a < bb) : (a > bb)) { sk[w][i] = bb; sk[w][p] = a; }
                }
            }
            __syncwarp();
        }
    }
    for (u32 i = lane; i < cnt; i += 32) g_keys[off + i] = sk[w][i];
}

__device__ __forceinline__ bool bit_test(const u32* bits, int i) {
    return (bits[i >> 5] >> (i & 31)) & 1u;
}

// greedy scan over globally-descending keys + exact fallback + output
__global__ void __launch_bounds__(1024, 1)
k_final(const float* __restrict__ cost, float* __restrict__ out, int out_size) {
    __shared__ u32 sFlat[STAGE_KEYS];          // 40960 B
    __shared__ u32 sConf[STAGE_WINS];          // 1280 B
    __shared__ u32 colUsed[NCOLS / 32];        // 2048 B
    __shared__ u32 rowUsed[NROWS / 32];        // 128 B
    __shared__ unsigned short colOf[NROWS];    // 2048 B
    __shared__ u64 redBuf[32];
    __shared__ int scnt_s;

    int tid = threadIdx.x;
    int lane = tid & 31;
    int wid = tid >> 5;
    u32 total = g_total;
    if (g_overflow) total = 0;   // pathological: pure-fallback path (exact)

    for (int i = tid; i < NCOLS / 32; i += 1024) colUsed[i] = 0;
    for (int i = tid; i < NROWS / 32; i += 1024) rowUsed[i] = 0;
    for (int i = tid; i < NROWS; i += 1024) colOf[i] = 0;
    if (tid == 0) scnt_s = 0;

    // ---- stage first STAGE_KEYS flats into shared (all warps) ----
    for (int i = tid; i < STAGE_KEYS; i += 1024)
        sFlat[i] = (i < (int)total) ? (0xFFFFFFu - (u32)(g_keys[i] & 0xFFFFFFu))
                                    : FLAT_INVALID;
    __syncthreads();

    // ---- precompute per-window conflict masks (all warps in parallel) ----
    // conf bit = lane shares row or col with ANY earlier lane in its window.
    for (int w = wid; w < STAGE_WINS; w += 32) {
        u32 flat = sFlat[w * 32 + lane];
        bool v = (flat != FLAT_INVALID);
        u32 rkey = v ? (flat >> 14) : (u32)(NROWS + lane);
        u32 ckey = v ? (flat & 0x3FFF) : (u32)(NCOLS + lane);
        u32 mR = __match_any_sync(0xFFFFFFFFu, rkey);
        u32 mC = __match_any_sync(0xFFFFFFFFu, ckey);
        u32 earlier = (1u << lane) - 1u;
        bool conf = (((mR | mC) & earlier) != 0u);
        u32 cm = __ballot_sync(0xFFFFFFFFu, conf);
        if (lane == 0) sConf[w] = cm;
    }
    __syncthreads();

    // ---- warp 0: greedy scan, ONE ballot per window ----
    // accmask = valid & ~conf  : exactly greedy-accepted (no conflict with any
    //   earlier in-window lane, rows/cols free) and pairwise distinct -> commit
    //   in parallel. questmask = valid & conf resolved serially in lane order
    //   against current state — exact greedy order (accept0 lanes share nothing
    //   with earlier lanes, so committing them first can't change quest outcomes).
    if (wid == 0) {
        int assigned = 0;
        int lim = ((int)total < STAGE_KEYS) ? (int)total : STAGE_KEYS;
        int base = 0;
        u32 flat = (0 < lim) ? sFlat[lane] : FLAT_INVALID;
        for (; base < lim && assigned < NROWS; base += 32) {
            u32 nflat = (base + 32 < STAGE_KEYS) ? sFlat[base + 32 + lane] : FLAT_INVALID;
            u32 conf = sConf[base >> 5];
            int r = (int)(flat >> 14);
            int c = (int)(flat & 0x3FFF);
            u32 rw = rowUsed[r >> 5];            // two INDEPENDENT LDS,
            u32 cw = colUsed[c >> 5];            // issued in parallel
            bool valid = (flat != FLAT_INVALID) &&
                         !((rw >> (r & 31)) & 1u) && !((cw >> (c & 31)) & 1u);
            u32 validmask = __ballot_sync(0xFFFFFFFFu, valid);
            u32 accmask = validmask & ~conf;
            if ((accmask >> lane) & 1u) {
                atomicOr(&rowUsed[r >> 5], 1u << (r & 31));
                atomicOr(&colUsed[c >> 5], 1u << (c & 31));
                colOf[r] = (unsigned short)c;
            }
            assigned += __popc(accmask);

            u32 quest = validmask & conf;
            if (quest) {                          // warp-uniform, rare (~28% windows)
                __syncwarp();
                while (quest) {
                    int q = __ffs(quest) - 1;
                    quest &= quest - 1u;
                    int qr = __shfl_sync(0xFFFFFFFFu, r, q);
                    int qc = __shfl_sync(0xFFFFFFFFu, c, q);
                    bool ok = !bit_test(rowUsed, qr) && !bit_test(colUsed, qc);
                    if (ok) {
                        if (lane == 0) {
                            atomicOr(&rowUsed[qr >> 5], 1u << (qr & 31));
                            atomicOr(&colUsed[qc >> 5], 1u << (qc & 31));
                            colOf[qr] = (unsigned short)qc;
                        }
                        assigned++;
                        __syncwarp();
                    }
                }
            }
            __syncwarp();                         // commit visibility for next window
            flat = nflat;
        }
        // ---- legacy gmem tail (only if staged prefix exhausted) ----
        for (; base < (int)total && assigned < NROWS; base += 32) {
            int i = base + lane;
            u64 key = (i < (int)total) ? __ldg(&g_keys[i]) : 0ull;
            int flat2 = 0xFFFFFF - (int)(key & 0xFFFFFFu);
            int r = flat2 >> 14;
            int c = flat2 & 0x3FFF;
            bool valid = (key != 0ull) && !bit_test(rowUsed, r) && !bit_test(colUsed, c);
            u32 validmask = __ballot_sync(0xFFFFFFFFu, valid);
            u32 rkey = valid ? (u32)r : (u32)(NROWS + lane);
            u32 ckey = valid ? (u32)c : (u32)(NCOLS + lane);
            u32 mR = __match_any_sync(0xFFFFFFFFu, rkey);
            u32 mC = __match_any_sync(0xFFFFFFFFu, ckey);
            u32 earlier = (1u << lane) - 1u;
            bool conflictE = (((mR | mC) & earlier & validmask) != 0u);
            bool acc0 = valid && !conflictE;
            u32 accmask = __ballot_sync(0xFFFFFFFFu, acc0);
            if (acc0) {
                atomicOr(&rowUsed[r >> 5], 1u << (r & 31));
                atomicOr(&colUsed[c >> 5], 1u << (c & 31));
                colOf[r] = (unsigned short)c;
            }
            assigned += __popc(accmask);
            __syncwarp();
            u32 quest = __ballot_sync(0xFFFFFFFFu, valid && conflictE);
            while (quest) {
                int q = __ffs(quest) - 1;
                quest &= quest - 1u;
                int qr = __shfl_sync(0xFFFFFFFFu, r, q);
                int qc = __shfl_sync(0xFFFFFFFFu, c, q);
                bool ok = !bit_test(rowUsed, qr) && !bit_test(colUsed, qc);
                if (ok) {
                    if (lane == 0) {
                        atomicOr(&rowUsed[qr >> 5], 1u << (qr & 31));
                        atomicOr(&colUsed[qc >> 5], 1u << (qc & 31));
                        colOf[qr] = (unsigned short)qc;
                    }
                    assigned++;
                    __syncwarp();
                }
            }
        }
        if (lane == 0) scnt_s = assigned;
    }

    // ---- exact fallback: masked global argmax for any unassigned rows ----
    while (true) {
        __syncthreads();
        if (scnt_s >= NROWS) break;
        u64 best = 0;
        for (int i = tid; i < NTOT; i += 1024) {
            int r = i >> 14;
            if (bit_test(rowUsed, r)) continue;
            int c = i & 0x3FFF;
            if (bit_test(colUsed, c)) continue;
            float v = cost[i];
            u32 u = __float_as_uint(v);
            u32 enc = (u & 0x80000000u) ? ~u : (u | 0x80000000u);
            u64 kk = ((u64)enc << 24) | (u64)(0xFFFFFFu - (u32)i);
            if (kk > best) best = kk;
        }
        #pragma unroll
        for (int o = 16; o > 0; o >>= 1) {
            u64 t2 = __shfl_down_sync(0xFFFFFFFFu, best, o);
            if (t2 > best) best = t2;
        }
        if (lane == 0) redBuf[wid] = best;
        __syncthreads();
        if (tid < 32) {
            u64 b = redBuf[tid];
            #pragma unroll
            for (int o = 16; o > 0; o >>= 1) {
                u64 t2 = __shfl_down_sync(0xFFFFFFFFu, b, o);
                if (t2 > b) b = t2;
            }
            if (tid == 0) {
                int flat = 0xFFFFFF - (int)(b & 0xFFFFFFu);
                int r = flat >> 14, c = flat & 0x3FFF;
                rowUsed[r >> 5] |= 1u << (r & 31);
                colUsed[c >> 5] |= 1u << (c & 31);
                colOf[r] = (unsigned short)c;
                scnt_s = scnt_s + 1;
            }
        }
        __syncthreads();
    }

    // ---- write output as float32: rows (arange) then cols ----
    if (out_size >= 2 * NROWS) {
        for (int i = tid; i < NROWS; i += 1024) {
            out[i] = (float)i;
            out[NROWS + i] = (float)colOf[i];
        }
    } else {
        for (int i = tid; i < NROWS && i < out_size; i += 1024)
            out[i] = (float)colOf[i];
    }

    // ---- self-clean for next call ----
    if (tid == 0) { g_total = 0; g_overflow = 0; }
}

extern "C" void kernel_launch(void* const* d_in, const int* in_sizes, int n_in,
                              void* d_out, int out_size) {
    const float* cost = (const float*)d_in[0];
    float* out = (float*)d_out;
    (void)in_sizes; (void)n_in;

    k_scatter<<<SC_GRID, SC_BLK>>>((const float4*)cost);
    k_scan<<<1, 1024>>>();
    k_sortbins<<<FBINS / SB_WARPS, SB_WARPS * 32>>>();
    k_final<<<1, 1024>>>(cost, out, out_size);
}

// round 12
// speedup vs baseline: 1.7214x; 1.6131x over previous
#include <cuda_runtime.h>
#include <cstdint>

typedef unsigned long long u64;
typedef unsigned int u32;

#define NROWS 1024
#define NCOLS 16384
#define NTOT (NROWS*NCOLS)
#define CAP 32768
#define FBINS 4096
#define HLO 2.0f
#define HSCALE 1024.0f
#define BIN_MIN 1060      // value threshold ~= 3.035
#define BCAP 128

#define SC_GRID 4096
#define SC_BLK 256
#define SC_STRIDE (SC_GRID*SC_BLK)   // NTOT/4 = 4*SC_STRIDE exactly

#define STAGE_KEYS 10240
#define PHA_KEYS 2048
#define PHA_WINS (PHA_KEYS/32)          // 64
#define COMP_CHUNKS ((STAGE_KEYS-PHA_KEYS)/1024)  // 8
#define MAXB_WINS ((STAGE_KEYS-PHA_KEYS+31)/32)   // 256
#define FLAT_INVALID 0xFFFFFFFFu

#define SB_WARPS 8

// device-global scratch (no allocations allowed)
// Self-cleaning invariant: at kernel_launch entry, g_bincnt[]==0 and
// g_total==g_overflow==0 (zero-init at load; re-established every call).
__device__ u32 g_bincnt[FBINS];
__device__ u32 g_binoff[FBINS];
__device__ u32 g_total;
__device__ u32 g_overflow;
__device__ u64 g_bucket[FBINS * BCAP];   // 4 MB
__device__ u64 g_keys[CAP];

__device__ __forceinline__ int binof(float v) {
    int b = (int)((v - HLO) * HSCALE);
    return (b > FBINS - 1) ? (FBINS - 1) : b;
}

// ONE full-matrix pass: scatter candidates (binof(v) >= BIN_MIN) into buckets
__global__ void __launch_bounds__(SC_BLK)
k_scatter(const float4* __restrict__ c4) {
    int idx = blockIdx.x * SC_BLK + threadIdx.x;
    float4 vv[4];
    #pragma unroll
    for (int k = 0; k < 4; k++) vv[k] = c4[idx + k * SC_STRIDE];   // MLP=4
    #pragma unroll
    for (int k = 0; k < 4; k++) {
        int i = idx + k * SC_STRIDE;
        float a[4] = { vv[k].x, vv[k].y, vv[k].z, vv[k].w };
        #pragma unroll
        for (int q = 0; q < 4; q++) {
            if (a[q] >= 3.0f) {
                int b = binof(a[q]);
                if (b >= BIN_MIN) {
                    u32 pos = atomicAdd(&g_bincnt[b], 1u);
                    if (pos < BCAP) {
                        u32 flat = (u32)(i * 4 + q);
                        u32 enc = __float_as_uint(a[q]);  // candidates > 0: bits order-preserving
                        g_bucket[b * BCAP + pos] = ((u64)enc << 24) | (u64)(0xFFFFFFu - flat);
                    } else {
                        g_overflow = 1;
                    }
                }
            }
        }
    }
}

// one block: suffix-sum bucket counts (descending bins) via shuffle scan
__global__ void __launch_bounds__(1024)
k_scan() {
    __shared__ u32 warpsum[32];
    int tid = threadIdx.x;
    int lane = tid & 31, w = tid >> 5;

    u32 x[4], pre[4];
    u32 run = 0;
    #pragma unroll
    for (int q = 0; q < 4; q++) {
        int b = FBINS - 1 - (tid * 4 + q);
        x[q] = g_bincnt[b];
        pre[q] = run;
        run += x[q];
    }
    u32 v = run;
    #pragma unroll
    for (int o = 1; o < 32; o <<= 1) {
        u32 t = __shfl_up_sync(0xFFFFFFFFu, v, o);
        if (lane >= o) v += t;
    }
    if (lane == 31) warpsum[w] = v;
    __syncthreads();
    if (w == 0) {
        u32 s = warpsum[lane];
        #pragma unroll
        for (int o = 1; o < 32; o <<= 1) {
            u32 t = __shfl_up_sync(0xFFFFFFFFu, s, o);
            if (lane >= o) s += t;
        }
        warpsum[lane] = s;
    }
    __syncthreads();
    u32 excl = v - run + ((w > 0) ? warpsum[w - 1] : 0u);

    #pragma unroll
    for (int q = 0; q < 4; q++) {
        int b = FBINS - 1 - (tid * 4 + q);
        u32 S = excl + pre[q] + x[q];
        g_binoff[b] = S - x[q];
    }
    if (tid == 0) {
        u32 total = warpsum[31];
        if (total > CAP) { g_overflow = 1; total = 0; }
        g_total = total;
    }
}

// warp-per-bin: sort bucket desc (<=128 elems) into g_keys; self-clean bincnt
__global__ void __launch_bounds__(SB_WARPS * 32)
k_sortbins() {
    __shared__ u64 sk[SB_WARPS][BCAP];
    int w = threadIdx.x >> 5, lane = threadIdx.x & 31;
    int b = blockIdx.x * SB_WARPS + w;
    u32 cnt = g_bincnt[b];
    if (lane == 0) g_bincnt[b] = 0;          // self-clean for next call
    if (cnt == 0) return;
    if (cnt > BCAP) cnt = BCAP;              // overflow already flagged; data unused
    u32 off = g_binoff[b];
    if (cnt == 1) { if (lane == 0) g_keys[off] = g_bucket[b * BCAP]; return; }

    u32 m = 2; while (m < cnt) m <<= 1;      // m <= 128
    for (u32 i = lane; i < m; i += 32) sk[w][i] = (i < cnt) ? g_bucket[b * BCAP + i] : 0ull;
    __syncwarp();
    for (u32 k = 2; k <= m; k <<= 1) {
        for (u32 j = k >> 1; j > 0; j >>= 1) {
            for (u32 i = lane; i < m; i += 32) {
                u32 p = i ^ j;
                if (p > i) {
                    u64 a = sk[w][i], bb = sk[w][p];
                    bool desc = ((i & k) == 0);
                    if (desc ? (a < bb) : (a > bb)) { sk[w][i] = bb; sk[w][p] = a; }
                }
            }
            __syncwarp();
        }
    }
    for (u32 i = lane; i < cnt; i += 32) g_keys[off + i] = sk[w][i];
}

__device__ __forceinline__ bool bit_test(const u32* bits, int i) {
    return (bits[i >> 5] >> (i & 31)) & 1u;
}

// greedy scan over globally-descending keys + exact fallback + output
__global__ void __launch_bounds__(1024, 1)
k_final(const float* __restrict__ cost, float* __restrict__ out, int out_size) {
    __shared__ u32 sFlat[STAGE_KEYS];          // 40960 B
    __shared__ u32 sConfA[PHA_WINS];           // 256 B
    __shared__ u32 sConfB[MAXB_WINS];          // 1024 B
    __shared__ unsigned char rowUsedB[NROWS];  // 1024 B
    __shared__ u32 colUsed[NCOLS / 32];        // 2048 B
    __shared__ unsigned short colOf[NROWS];    // 2048 B
    __shared__ u32 warpS[32];
    __shared__ u64 redBuf[32];
    __shared__ int scnt_s, m2_s;

    int tid = threadIdx.x;
    int lane = tid & 31;
    int wid = tid >> 5;
    u32 total = g_total;
    if (g_overflow) total = 0;   // pathological: pure-fallback path (exact)

    for (int i = tid; i < NCOLS / 32; i += 1024) colUsed[i] = 0;
    for (int i = tid; i < NROWS; i += 1024) { rowUsedB[i] = 0; colOf[i] = 0; }
    if (tid == 0) { scnt_s = 0; m2_s = 0; }

    // ---- stage first STAGE_KEYS flats into shared (all warps) ----
    for (int i = tid; i < STAGE_KEYS; i += 1024)
        sFlat[i] = (i < (int)total) ? (0xFFFFFFu - (u32)(g_keys[i] & 0xFFFFFFu))
                                    : FLAT_INVALID;
    __syncthreads();

    // ---- precompute phase-A conflict masks (warps in parallel; 2 per warp) ----
    for (int w = wid; w < PHA_WINS; w += 32) {
        u32 flat = sFlat[w * 32 + lane];
        bool v = (flat != FLAT_INVALID);
        u32 rkey = v ? (flat >> 14) : (u32)(NROWS + lane);
        u32 ckey = v ? (flat & 0x3FFF) : (u32)(NCOLS + lane);
        u32 mR = __match_any_sync(0xFFFFFFFFu, rkey);
        u32 mC = __match_any_sync(0xFFFFFFFFu, ckey);
        u32 earlier = (1u << lane) - 1u;
        bool conf = (((mR | mC) & earlier) != 0u);
        u32 cm = __ballot_sync(0xFFFFFFFFu, conf);
        if (lane == 0) sConfA[w] = cm;
    }
    __syncthreads();

    // ================= PHASE A: warp 0, first PHA_KEYS keys =================
    // accmask = valid & ~conf: exactly greedy-accepted, pairwise row/col-
    // distinct -> parallel commit (row flags are BYTES: distinct rows => plain
    // store; col flags bit-array via atomicOr). quest lanes resolved serially
    // in lane order vs current state — exact greedy order.
    if (wid == 0) {
        int assigned = 0;
        int lim = ((int)total < PHA_KEYS) ? (int)total : PHA_KEYS;
        u32 flat = (0 < lim) ? sFlat[lane] : FLAT_INVALID;
        for (int base = 0; base < lim && assigned < NROWS; base += 32) {
            u32 nflat = (base + 32 < PHA_KEYS) ? sFlat[base + 32 + lane] : FLAT_INVALID;
            u32 conf = sConfA[base >> 5];
            int r = (int)(flat >> 14);
            int c = (int)(flat & 0x3FFF);
            unsigned char rb = rowUsedB[r];
            u32 cw = colUsed[c >> 5];
            bool valid = (flat != FLAT_INVALID) && !rb && !((cw >> (c & 31)) & 1u);
            u32 validmask = __ballot_sync(0xFFFFFFFFu, valid);
            u32 accmask = validmask & ~conf;
            if ((accmask >> lane) & 1u) {
                rowUsedB[r] = 1;
                atomicOr(&colUsed[c >> 5], 1u << (c & 31));
                colOf[r] = (unsigned short)c;
            }
            assigned += __popc(accmask);

            u32 quest = validmask & conf;
            if (quest) {
                __syncwarp();
                while (quest) {
                    int q = __ffs(quest) - 1;
                    quest &= quest - 1u;
                    int qr = __shfl_sync(0xFFFFFFFFu, r, q);
                    int qc = __shfl_sync(0xFFFFFFFFu, c, q);
                    bool ok = !rowUsedB[qr] && !bit_test(colUsed, qc);
                    if (ok) {
                        if (lane == 0) {
                            rowUsedB[qr] = 1;
                            atomicOr(&colUsed[qc >> 5], 1u << (qc & 31));
                            colOf[qr] = (unsigned short)qc;
                        }
                        assigned++;
                        __syncwarp();
                    }
                }
            }
            __syncwarp();
            flat = nflat;
        }
        if (lane == 0) scnt_s = assigned;
    }
    __syncthreads();

    // ====== MID-SCAN COMPACTION (all threads): keep keys in [PHA_KEYS,
    // STAGE_KEYS) whose row AND col are still free; order-preserving.
    // Dropping row/col-dead keys is greedy-neutral; writes land in
    // sFlat[0 .. m2) which never overlaps the not-yet-read region. ======
    {
        int m2base = 0;
        for (int k = 0; k < COMP_CHUNKS; k++) {
            int idx = PHA_KEYS + k * 1024 + tid;
            u32 f = sFlat[idx];
            bool keep = (f != FLAT_INVALID) && !rowUsedB[f >> 14] && !bit_test(colUsed, f & 0x3FFF);
            u32 ball = __ballot_sync(0xFFFFFFFFu, keep);
            int myoff = __popc(ball & ((1u << lane) - 1u));
            if (lane == 0) warpS[wid] = (u32)__popc(ball);
            __syncthreads();
            if (tid < 32) {
                u32 v = warpS[tid];
                #pragma unroll
                for (int o = 1; o < 32; o <<= 1) {
                    u32 t2 = __shfl_up_sync(0xFFFFFFFFu, v, o);
                    if (tid >= o) v += t2;
                }
                warpS[tid] = v;
            }
            __syncthreads();
            int wexcl = (wid > 0) ? (int)warpS[wid - 1] : 0;
            int chunkTot = (int)warpS[31];
            if (keep) sFlat[m2base + wexcl + myoff] = f;
            m2base += chunkTot;
            __syncthreads();
        }
        if (tid == 0) m2_s = m2base;
    }
    __syncthreads();

    // ---- precompute phase-B conflict masks over compacted list ----
    int m2 = m2_s;
    int nwinB = (m2 + 31) >> 5;
    for (int w = wid; w < nwinB; w += 32) {
        int i = w * 32 + lane;
        u32 flat = (i < m2) ? sFlat[i] : FLAT_INVALID;
        bool v = (flat != FLAT_INVALID);
        u32 rkey = v ? (flat >> 14) : (u32)(NROWS + lane);
        u32 ckey = v ? (flat & 0x3FFF) : (u32)(NCOLS + lane);
        u32 mR = __match_any_sync(0xFFFFFFFFu, rkey);
        u32 mC = __match_any_sync(0xFFFFFFFFu, ckey);
        u32 earlier = (1u << lane) - 1u;
        bool conf = (((mR | mC) & earlier) != 0u);
        u32 cm = __ballot_sync(0xFFFFFFFFu, conf);
        if (lane == 0) sConfB[w] = cm;
    }
    __syncthreads();

    // ================= PHASE B: warp 0, compacted keys =================
    if (wid == 0) {
        int assigned = scnt_s;
        u32 flat = (0 < m2 && lane < m2) ? sFlat[lane] : FLAT_INVALID;
        for (int base = 0; base < m2 && assigned < NROWS; base += 32) {
            int ni = base + 32 + lane;
            u32 nflat = (ni < m2) ? sFlat[ni] : FLAT_INVALID;
            u32 conf = sConfB[base >> 5];
            int r = (int)(flat >> 14);
            int c = (int)(flat & 0x3FFF);
            unsigned char rb = (flat != FLAT_INVALID) ? rowUsedB[r] : (unsigned char)1;
            u32 cw = colUsed[(c & 0x3FFF) >> 5];
            bool valid = (flat != FLAT_INVALID) && !rb && !((cw >> (c & 31)) & 1u);
            u32 validmask = __ballot_sync(0xFFFFFFFFu, valid);
            u32 accmask = validmask & ~conf;
            if ((accmask >> lane) & 1u) {
                rowUsedB[r] = 1;
                atomicOr(&colUsed[c >> 5], 1u << (c & 31));
                colOf[r] = (unsigned short)c;
            }
            assigned += __popc(accmask);

            u32 quest = validmask & conf;
            if (quest) {
                __syncwarp();
                while (quest) {
                    int q = __ffs(quest) - 1;
                    quest &= quest - 1u;
                    int qr = __shfl_sync(0xFFFFFFFFu, r, q);
                    int qc = __shfl_sync(0xFFFFFFFFu, c, q);
                    bool ok = !rowUsedB[qr] && !bit_test(colUsed, qc);
                    if (ok) {
                        if (lane == 0) {
                            rowUsedB[qr] = 1;
                            atomicOr(&colUsed[qc >> 5], 1u << (qc & 31));
                            colOf[qr] = (unsigned short)qc;
                        }
                        assigned++;
                        __syncwarp();
                    }
                }
            }
            __syncwarp();
            flat = nflat;
        }
        // ---- legacy gmem tail (only if staged prefix exhausted) ----
        for (int base = STAGE_KEYS; base < (int)total && assigned < NROWS; base += 32) {
            int i = base + lane;
            u64 key = (i < (int)total) ? __ldg(&g_keys[i]) : 0ull;
            int flat2 = 0xFFFFFF - (int)(key & 0xFFFFFFu);
            int r = flat2 >> 14;
            int c = flat2 & 0x3FFF;
            bool valid = (key != 0ull) && !rowUsedB[r] && !bit_test(colUsed, c);
            u32 validmask = __ballot_sync(0xFFFFFFFFu, valid);
            u32 rkey = valid ? (u32)r : (u32)(NROWS + lane);
            u32 ckey = valid ? (u32)c : (u32)(NCOLS + lane);
            u32 mR = __match_any_sync(0xFFFFFFFFu, rkey);
            u32 mC = __match_any_sync(0xFFFFFFFFu, ckey);
            u32 earlier = (1u << lane) - 1u;
            bool conflictE = (((mR | mC) & earlier & validmask) != 0u);
            bool acc0 = valid && !conflictE;
            u32 accmask = __ballot_sync(0xFFFFFFFFu, acc0);
            if (acc0) {
                rowUsedB[r] = 1;
                atomicOr(&colUsed[c >> 5], 1u << (c & 31));
                colOf[r] = (unsigned short)c;
            }
            assigned += __popc(accmask);
            __syncwarp();
            u32 quest = __ballot_sync(0xFFFFFFFFu, valid && conflictE);
            while (quest) {
                int q = __ffs(quest) - 1;
                quest &= quest - 1u;
                int qr = __shfl_sync(0xFFFFFFFFu, r, q);
                int qc = __shfl_sync(0xFFFFFFFFu, c, q);
                bool ok = !rowUsedB[qr] && !bit_test(colUsed, qc);
                if (ok) {
                    if (lane == 0) {
                        rowUsedB[qr] = 1;
                        atomicOr(&colUsed[qc >> 5], 1u << (qc & 31));
                        colOf[qr] = (unsigned short)qc;
                    }
                    assigned++;
                    __syncwarp();
                }
            }
        }
        if (lane == 0) scnt_s = assigned;
    }

    // ---- exact fallback: masked global argmax for any unassigned rows ----
    while (true) {
        __syncthreads();
        if (scnt_s >= NROWS) break;
        u64 best = 0;
        for (int i = tid; i < NTOT; i += 1024) {
            int r = i >> 14;
            if (rowUsedB[r]) continue;
            int c = i & 0x3FFF;
            if (bit_test(colUsed, c)) continue;
            float v = cost[i];
            u32 u = __float_as_uint(v);
            u32 enc = (u & 0x80000000u) ? ~u : (u | 0x80000000u);
            u64 kk = ((u64)enc << 24) | (u64)(0xFFFFFFu - (u32)i);
            if (kk > best) best = kk;
        }
        #pragma unroll
        for (int o = 16; o > 0; o >>= 1) {
            u64 t2 = __shfl_down_sync(0xFFFFFFFFu, best, o);
            if (t2 > best) best = t2;
        }
        if (lane == 0) redBuf[wid] = best;
        __syncthreads();
        if (tid < 32) {
            u64 b = redBuf[tid];
            #pragma unroll
            for (int o = 16; o > 0; o >>= 1) {
                u64 t2 = __shfl_down_sync(0xFFFFFFFFu, b, o);
                if (t2 > b) b = t2;
            }
            if (tid == 0) {
                int flat = 0xFFFFFF - (int)(b & 0xFFFFFFu);
                int r = flat >> 14, c = flat & 0x3FFF;
                rowUsedB[r] = 1;
                colUsed[c >> 5] |= 1u << (c & 31);
                colOf[r] = (unsigned short)c;
                scnt_s = scnt_s + 1;
            }
        }
        __syncthreads();
    }

    // ---- write output as float32: rows (arange) then cols ----
    if (out_size >= 2 * NROWS) {
        for (int i = tid; i < NROWS; i += 1024) {
            out[i] = (float)i;
            out[NROWS + i] = (float)colOf[i];
        }
    } else {
        for (int i = tid; i < NROWS && i < out_size; i += 1024)
            out[i] = (float)colOf[i];
    }

    // ---- self-clean for next call ----
    if (tid == 0) { g_total = 0; g_overflow = 0; }
}

extern "C" void kernel_launch(void* const* d_in, const int* in_sizes, int n_in,
                              void* d_out, int out_size) {
    const float* cost = (const float*)d_in[0];
    float* out = (float*)d_out;
    (void)in_sizes; (void)n_in;

    k_scatter<<<SC_GRID, SC_BLK>>>((const float4*)cost);
    k_scan<<<1, 1024>>>();
    k_sortbins<<<FBINS / SB_WARPS, SB_WARPS * 32>>>();
    k_final<<<1, 1024>>>(cost, out, out_size);
}